// round 14
// baseline (speedup 1.0000x reference)
#include <cuda_runtime.h>

#define B   8
#define C   1024
#define HW  4096
#define K   16

// Scratch (no allocations allowed) — fully rewritten every launch.
__device__ float g_num[B * K * C];      // masked class sums
__device__ float g_protoN[B * K * C];   // prototypes / (count * ||proto||)
__device__ int   g_counts[B * (K + 1)]; // per-class pixel counts (incl. class 0)

// ---------------------------------------------------------------------------
// K1: per-batch class histogram of the support mask (separate kernel: keeps
// serial atomic work OFF the bulk proto_sum critical path — R13 lesson).
// ---------------------------------------------------------------------------
__global__ void __launch_bounds__(256) hist_kernel(const int* __restrict__ masks) {
    __shared__ int h[K + 1];
    const int b   = blockIdx.x;
    const int tid = threadIdx.x;
    if (tid <= K) h[tid] = 0;
    __syncthreads();
    for (int p = tid; p < HW; p += 256) {
        int v = masks[b * HW + p];
        if (v >= 0 && v <= K) atomicAdd(&h[v], 1);   // guarded: never traps
    }
    __syncthreads();
    if (tid <= K) g_counts[b * (K + 1) + tid] = h[tid];
}

// ---------------------------------------------------------------------------
// K2: masked per-class sums.  One warp = one channel; lane-private smem slots
// acc[class][tid] (bank = tid%32 -> conflict-free dynamic indexing).
// 4 float4 loads in flight per lane (2 KB/warp outstanding).
// ---------------------------------------------------------------------------
__global__ void __launch_bounds__(256) proto_sum_kernel(
        const float* __restrict__ feat, const int* __restrict__ masks) {
    __shared__ unsigned char cls[HW];       // 4 KB
    __shared__ float acc[K][256];           // 16 KB

    const int b    = blockIdx.y;
    const int tid  = threadIdx.x;
    const int warp = tid >> 5;
    const int lane = tid & 31;
    const int c    = blockIdx.x * 8 + warp;

#pragma unroll
    for (int k = 0; k < K; k++) acc[k][tid] = 0.0f;
    for (int p = tid; p < HW; p += 256) {
        int v = masks[b * HW + p];
        cls[p] = (unsigned char)((v >= 1 && v <= K) ? v : 0);  // guarded
    }
    __syncthreads();

    const float4* f4 = (const float4*)(feat + ((size_t)b * C + c) * HW);
    const uchar4* c4 = (const uchar4*)cls;

    for (int i = lane; i < HW / 4; i += 128) {
        float4 v0 = f4[i];
        float4 v1 = f4[i + 32];
        float4 v2 = f4[i + 64];
        float4 v3 = f4[i + 96];
        uchar4 m0 = c4[i];
        uchar4 m1 = c4[i + 32];
        uchar4 m2 = c4[i + 64];
        uchar4 m3 = c4[i + 96];
        if (m0.x) acc[m0.x - 1][tid] += v0.x;
        if (m0.y) acc[m0.y - 1][tid] += v0.y;
        if (m0.z) acc[m0.z - 1][tid] += v0.z;
        if (m0.w) acc[m0.w - 1][tid] += v0.w;
        if (m1.x) acc[m1.x - 1][tid] += v1.x;
        if (m1.y) acc[m1.y - 1][tid] += v1.y;
        if (m1.z) acc[m1.z - 1][tid] += v1.z;
        if (m1.w) acc[m1.w - 1][tid] += v1.w;
        if (m2.x) acc[m2.x - 1][tid] += v2.x;
        if (m2.y) acc[m2.y - 1][tid] += v2.y;
        if (m2.z) acc[m2.z - 1][tid] += v2.z;
        if (m2.w) acc[m2.w - 1][tid] += v2.w;
        if (m3.x) acc[m3.x - 1][tid] += v3.x;
        if (m3.y) acc[m3.y - 1][tid] += v3.y;
        if (m3.z) acc[m3.z - 1][tid] += v3.z;
        if (m3.w) acc[m3.w - 1][tid] += v3.w;
    }

#pragma unroll
    for (int k = 0; k < K; k++) {
        float s = acc[k][tid];
#pragma unroll
        for (int off = 16; off; off >>= 1)
            s += __shfl_down_sync(0xffffffffu, s, off);
        if (lane == 0) g_num[((size_t)b * K + k) * C + c] = s;
    }
}

// ---------------------------------------------------------------------------
// K3: g_protoN = (num/count) / ||num/count||.
// argmax_k dot(protoN_k, q) == argmax_k cosine_sim.
// ---------------------------------------------------------------------------
__global__ void __launch_bounds__(256) finalize_kernel() {
    const int b = blockIdx.y, k = blockIdx.x, tid = threadIdx.x;
    const int cnt = g_counts[b * (K + 1) + k + 1];
    const float invCnt = cnt > 0 ? 1.0f / (float)cnt : 0.0f;
    const float* num = g_num    + ((size_t)(b * K + k)) * C;
    float*       out = g_protoN + ((size_t)(b * K + k)) * C;

    float pv[4];
    float ss = 0.0f;
#pragma unroll
    for (int j = 0; j < 4; j++) {
        pv[j] = num[tid + j * 256] * invCnt;
        ss += pv[j] * pv[j];
    }

    __shared__ float red[8];
    __shared__ float s_inv;
#pragma unroll
    for (int off = 16; off; off >>= 1)
        ss += __shfl_down_sync(0xffffffffu, ss, off);
    if ((tid & 31) == 0) red[tid >> 5] = ss;
    __syncthreads();
    if (tid == 0) {
        float s = 0.0f;
#pragma unroll
        for (int w = 0; w < 8; w++) s += red[w];
        s_inv = s > 0.0f ? 1.0f / sqrtf(s) : 0.0f;
    }
    __syncthreads();
    const float inv = s_inv;
#pragma unroll
    for (int j = 0; j < 4; j++) out[tid + j * 256] = pv[j] * inv;
}

// ---------------------------------------------------------------------------
// K4: pixel-packed match, TRIPLE-buffered 4-channel batches.
// Thread = (slice, t): slice = (k_half, ch_quarter), t covers 4 consecutive
// pixels; q read via LDG.128 over pixels.  Rotation A/B/C keeps ~8 LDG.128
// outstanding at the consume point (1 KB/warp, 16 KB/SM > ~11.4 KB needed
// for peak DRAM) while staying at ~110 regs — inside the (256,2) 128-reg
// cap, so nothing spills (R13's 8-deep variant hit the cap and serialized).
// Reduction order identical to R11.
// ---------------------------------------------------------------------------
__device__ __forceinline__ void fma_batch(
        const float* __restrict__ spb, int c,
        const float4& v0, const float4& v1, const float4& v2, const float4& v3,
        unsigned long long (&acc2)[8][2]) {
    const ulonglong2 u0 = *(const ulonglong2*)&v0;   // (p0,p1),(p2,p3)
    const ulonglong2 u1 = *(const ulonglong2*)&v1;
    const ulonglong2 u2 = *(const ulonglong2*)&v2;
    const ulonglong2 u3 = *(const ulonglong2*)&v3;
#pragma unroll
    for (int kk = 0; kk < 8; kk++) {
        const float4 pk = *(const float4*)(spb + kk * C + c);  // LDS.128 bcast
        unsigned long long d0, d1, d2, d3;
        asm("mov.b64 %0, {%1, %1};" : "=l"(d0) : "f"(pk.x));
        asm("mov.b64 %0, {%1, %1};" : "=l"(d1) : "f"(pk.y));
        asm("mov.b64 %0, {%1, %1};" : "=l"(d2) : "f"(pk.z));
        asm("mov.b64 %0, {%1, %1};" : "=l"(d3) : "f"(pk.w));
        asm("fma.rn.f32x2 %0, %1, %2, %0;" : "+l"(acc2[kk][0]) : "l"(u0.x), "l"(d0));
        asm("fma.rn.f32x2 %0, %1, %2, %0;" : "+l"(acc2[kk][1]) : "l"(u0.y), "l"(d0));
        asm("fma.rn.f32x2 %0, %1, %2, %0;" : "+l"(acc2[kk][0]) : "l"(u1.x), "l"(d1));
        asm("fma.rn.f32x2 %0, %1, %2, %0;" : "+l"(acc2[kk][1]) : "l"(u1.y), "l"(d1));
        asm("fma.rn.f32x2 %0, %1, %2, %0;" : "+l"(acc2[kk][0]) : "l"(u2.x), "l"(d2));
        asm("fma.rn.f32x2 %0, %1, %2, %0;" : "+l"(acc2[kk][1]) : "l"(u2.y), "l"(d2));
        asm("fma.rn.f32x2 %0, %1, %2, %0;" : "+l"(acc2[kk][0]) : "l"(u3.x), "l"(d3));
        asm("fma.rn.f32x2 %0, %1, %2, %0;" : "+l"(acc2[kk][1]) : "l"(u3.y), "l"(d3));
    }
}

__device__ __forceinline__ void load4(const float* __restrict__ qb, int c,
                                      float4 (&buf)[4]) {
#pragma unroll
    for (int j = 0; j < 4; j++)
        buf[j] = *(const float4*)&qb[(size_t)(c + j) * HW];
}

__global__ void __launch_bounds__(256, 2) match_kernel(
        const float* __restrict__ q, float* __restrict__ out) {
    extern __shared__ __align__(16) char smem_raw[];
    float*              sp  = (float*)smem_raw;              // [K][C] = 64 KB
    unsigned long long* red = (unsigned long long*)smem_raw; // reuse: 32 KB

    const int b     = blockIdx.y;
    const int tid   = threadIdx.x;
    const int slice = tid >> 5;          // 0..7
    const int t     = tid & 31;          // 0..31
    const int kh    = slice & 1;         // protos [kh*8, kh*8+8)
    const int cq    = slice >> 1;        // channels [cq*256, cq*256+256)
    const int p     = blockIdx.x * 128 + t * 4;   // 4 consecutive pixels

    // stage all 16x1024 normalized prototypes
    const float4* pr4 = (const float4*)(g_protoN + (size_t)b * K * C);
    for (int i = tid; i < K * C / 4; i += 256)
        ((float4*)sp)[i] = pr4[i];
    __syncthreads();

    const float* qb  = q + ((size_t)b * C + cq * 256) * HW + p;
    const float* spb = sp + (kh * 8) * C + cq * 256;

    unsigned long long acc2[8][2];   // [kk][pixel-pair]
#pragma unroll
    for (int kk = 0; kk < 8; kk++) { acc2[kk][0] = 0ull; acc2[kk][1] = 0ull; }

    float4 A[4], Bv[4], Cv[4];
    load4(qb, 0, A);                 // prologue: 2 batches in flight
    load4(qb, 4, Bv);

#pragma unroll 4
    for (int c = 0; c < 256; c += 12) {
        // steady state: issue C(c+8), compute A(c)  -> ~8 loads outstanding
        if (c + 8 < 256)  load4(qb, c + 8, Cv);
        fma_batch(spb, c, A[0], A[1], A[2], A[3], acc2);
        if (c + 12 < 256) load4(qb, c + 12, A);
        if (c + 4 < 256)  fma_batch(spb, c + 4, Bv[0], Bv[1], Bv[2], Bv[3], acc2);
        if (c + 16 < 256) load4(qb, c + 16, Bv);
        if (c + 8 < 256)  fma_batch(spb, c + 8, Cv[0], Cv[1], Cv[2], Cv[3], acc2);
    }
    // 256 = 12*21 + 4: loop covers c=0..252 in steps of 12; the guards above
    // handle the ragged tail exactly once each (max c used: 252).

    // protos dead -> partials in smem, lane-contiguous: red[k][pair][cs][t]
    __syncthreads();
#pragma unroll
    for (int kk = 0; kk < 8; kk++) {
        const int k = kh * 8 + kk;
        red[((k * 2 + 0) * 4 + cq) * 32 + t] = acc2[kk][0];
        red[((k * 2 + 1) * 4 + cq) * 32 + t] = acc2[kk][1];
    }
    __syncthreads();

    // one thread per pixel: sum 4 channel-quarters (packed), pick lane, argmax
    if (tid < 128) {
        const int tt   = tid >> 2;        // source thread
        const int pair = (tid >> 1) & 1;
        const int lohi = tid & 1;
        float best = -3.0e38f;
        int   bi   = 0;
#pragma unroll
        for (int k = 0; k < K; k++) {
            const unsigned long long* r = red + (k * 2 + pair) * 4 * 32 + tt;
            unsigned long long s01, s23, s;
            asm("add.rn.f32x2 %0, %1, %2;" : "=l"(s01) : "l"(r[0]),   "l"(r[32]));
            asm("add.rn.f32x2 %0, %1, %2;" : "=l"(s23) : "l"(r[64]),  "l"(r[96]));
            asm("add.rn.f32x2 %0, %1, %2;" : "=l"(s)   : "l"(s01),    "l"(s23));
            float lo, hi;
            asm("mov.b64 {%0, %1}, %2;" : "=f"(lo), "=f"(hi) : "l"(s));
            const float v = lohi ? hi : lo;
            if (v > best) { best = v; bi = k; }
        }
        out[(size_t)b * HW + blockIdx.x * 128 + tid] = (float)bi;  // f32 output
    }
}

// ---------------------------------------------------------------------------
extern "C" void kernel_launch(void* const* d_in, const int* in_sizes, int n_in,
                              void* d_out, int out_size) {
    // masks is the unique B*HW = 32768-element input; its position fixes the
    // ordering of the two feature tensors.
    int mask_idx = 1;
    for (int i = 0; i < n_in; i++)
        if (in_sizes[i] == B * HW) { mask_idx = i; break; }

    const int*   masks = (const int*)d_in[mask_idx];
    const float* sfeat;
    const float* qfeat;
    if (mask_idx == 1)      { sfeat = (const float*)d_in[0]; qfeat = (const float*)d_in[2]; }
    else if (mask_idx == 2) { qfeat = (const float*)d_in[0]; sfeat = (const float*)d_in[1]; }
    else                    { qfeat = (const float*)d_in[1]; sfeat = (const float*)d_in[2]; }
    float* out = (float*)d_out;
    (void)out_size;

    hist_kernel<<<B, 256>>>(masks);
    proto_sum_kernel<<<dim3(C / 8, B), 256>>>(sfeat, masks);
    finalize_kernel<<<dim3(K, B), 256>>>();

    static int smem_set = 0;
    if (!smem_set) {
        cudaFuncSetAttribute(match_kernel,
                             cudaFuncAttributeMaxDynamicSharedMemorySize,
                             K * C * (int)sizeof(float));
        smem_set = 1;
    }
    match_kernel<<<dim3(HW / 128, B), 256, K * C * sizeof(float)>>>(qfeat, out);
}

// round 15
// speedup vs baseline: 1.0440x; 1.0440x over previous
#include <cuda_runtime.h>

#define B   8
#define C   1024
#define HW  4096
#define K   16

// Scratch (no allocations allowed) — fully rewritten every launch.
__device__ float g_num[B * K * C];      // masked class sums
__device__ float g_protoN[B * K * C];   // prototypes / (count * ||proto||)
__device__ int   g_counts[B * (K + 1)]; // per-class pixel counts (incl. class 0)

// ---------------------------------------------------------------------------
// K1: per-batch class histogram of the support mask (separate kernel: keeps
// serial atomic work OFF the bulk proto_sum critical path — R13 lesson).
// ---------------------------------------------------------------------------
__global__ void __launch_bounds__(256) hist_kernel(const int* __restrict__ masks) {
    __shared__ int h[K + 1];
    const int b   = blockIdx.x;
    const int tid = threadIdx.x;
    if (tid <= K) h[tid] = 0;
    __syncthreads();
    for (int p = tid; p < HW; p += 256) {
        int v = masks[b * HW + p];
        if (v >= 0 && v <= K) atomicAdd(&h[v], 1);   // guarded: never traps
    }
    __syncthreads();
    if (tid <= K) g_counts[b * (K + 1) + tid] = h[tid];
}

// ---------------------------------------------------------------------------
// K2: masked per-class sums.  One warp = one channel; lane-private smem slots
// acc[class][tid] (bank = tid%32 -> conflict-free dynamic indexing).
// 4 float4 loads in flight per lane (2 KB/warp outstanding).
// ---------------------------------------------------------------------------
__global__ void __launch_bounds__(256) proto_sum_kernel(
        const float* __restrict__ feat, const int* __restrict__ masks) {
    __shared__ unsigned char cls[HW];       // 4 KB
    __shared__ float acc[K][256];           // 16 KB

    const int b    = blockIdx.y;
    const int tid  = threadIdx.x;
    const int warp = tid >> 5;
    const int lane = tid & 31;
    const int c    = blockIdx.x * 8 + warp;

#pragma unroll
    for (int k = 0; k < K; k++) acc[k][tid] = 0.0f;
    for (int p = tid; p < HW; p += 256) {
        int v = masks[b * HW + p];
        cls[p] = (unsigned char)((v >= 1 && v <= K) ? v : 0);  // guarded
    }
    __syncthreads();

    const float4* f4 = (const float4*)(feat + ((size_t)b * C + c) * HW);
    const uchar4* c4 = (const uchar4*)cls;

    for (int i = lane; i < HW / 4; i += 128) {
        float4 v0 = f4[i];
        float4 v1 = f4[i + 32];
        float4 v2 = f4[i + 64];
        float4 v3 = f4[i + 96];
        uchar4 m0 = c4[i];
        uchar4 m1 = c4[i + 32];
        uchar4 m2 = c4[i + 64];
        uchar4 m3 = c4[i + 96];
        if (m0.x) acc[m0.x - 1][tid] += v0.x;
        if (m0.y) acc[m0.y - 1][tid] += v0.y;
        if (m0.z) acc[m0.z - 1][tid] += v0.z;
        if (m0.w) acc[m0.w - 1][tid] += v0.w;
        if (m1.x) acc[m1.x - 1][tid] += v1.x;
        if (m1.y) acc[m1.y - 1][tid] += v1.y;
        if (m1.z) acc[m1.z - 1][tid] += v1.z;
        if (m1.w) acc[m1.w - 1][tid] += v1.w;
        if (m2.x) acc[m2.x - 1][tid] += v2.x;
        if (m2.y) acc[m2.y - 1][tid] += v2.y;
        if (m2.z) acc[m2.z - 1][tid] += v2.z;
        if (m2.w) acc[m2.w - 1][tid] += v2.w;
        if (m3.x) acc[m3.x - 1][tid] += v3.x;
        if (m3.y) acc[m3.y - 1][tid] += v3.y;
        if (m3.z) acc[m3.z - 1][tid] += v3.z;
        if (m3.w) acc[m3.w - 1][tid] += v3.w;
    }

#pragma unroll
    for (int k = 0; k < K; k++) {
        float s = acc[k][tid];
#pragma unroll
        for (int off = 16; off; off >>= 1)
            s += __shfl_down_sync(0xffffffffu, s, off);
        if (lane == 0) g_num[((size_t)b * K + k) * C + c] = s;
    }
}

// ---------------------------------------------------------------------------
// K3: g_protoN = (num/count) / ||num/count||.
// argmax_k dot(protoN_k, q) == argmax_k cosine_sim.
// ---------------------------------------------------------------------------
__global__ void __launch_bounds__(256) finalize_kernel() {
    const int b = blockIdx.y, k = blockIdx.x, tid = threadIdx.x;
    const int cnt = g_counts[b * (K + 1) + k + 1];
    const float invCnt = cnt > 0 ? 1.0f / (float)cnt : 0.0f;
    const float* num = g_num    + ((size_t)(b * K + k)) * C;
    float*       out = g_protoN + ((size_t)(b * K + k)) * C;

    float pv[4];
    float ss = 0.0f;
#pragma unroll
    for (int j = 0; j < 4; j++) {
        pv[j] = num[tid + j * 256] * invCnt;
        ss += pv[j] * pv[j];
    }

    __shared__ float red[8];
    __shared__ float s_inv;
#pragma unroll
    for (int off = 16; off; off >>= 1)
        ss += __shfl_down_sync(0xffffffffu, ss, off);
    if ((tid & 31) == 0) red[tid >> 5] = ss;
    __syncthreads();
    if (tid == 0) {
        float s = 0.0f;
#pragma unroll
        for (int w = 0; w < 8; w++) s += red[w];
        s_inv = s > 0.0f ? 1.0f / sqrtf(s) : 0.0f;
    }
    __syncthreads();
    const float inv = s_inv;
#pragma unroll
    for (int j = 0; j < 4; j++) out[tid + j * 256] = pv[j] * inv;
}

// ---------------------------------------------------------------------------
// K4: pixel-packed match — R11's exact double-buffered loop, but k split
// 4-way: slice = (k_quarter, ch_quarter), 16 slices x 16 threads x 4 px.
// acc2 shrinks 32->16 regs so total demand ~80 fits __launch_bounds__(256,3):
// 3 CTAs/SM (regs 256*85*3 <= 64K, smem 3*64 KB <= 228 KB) = 24 warps/SM,
// +50% latency hiding at unchanged pipeline depth.  Channel partitioning and
// quarter-sum tree unchanged -> bit-identical output to R11.
// ---------------------------------------------------------------------------
__device__ __forceinline__ void fma_batch(
        const float* __restrict__ spb, int c,
        const float4& v0, const float4& v1, const float4& v2, const float4& v3,
        unsigned long long (&acc2)[4][2]) {
    const ulonglong2 u0 = *(const ulonglong2*)&v0;   // (p0,p1),(p2,p3)
    const ulonglong2 u1 = *(const ulonglong2*)&v1;
    const ulonglong2 u2 = *(const ulonglong2*)&v2;
    const ulonglong2 u3 = *(const ulonglong2*)&v3;
#pragma unroll
    for (int kk = 0; kk < 4; kk++) {
        const float4 pk = *(const float4*)(spb + kk * C + c);  // LDS.128 bcast
        unsigned long long d0, d1, d2, d3;
        asm("mov.b64 %0, {%1, %1};" : "=l"(d0) : "f"(pk.x));
        asm("mov.b64 %0, {%1, %1};" : "=l"(d1) : "f"(pk.y));
        asm("mov.b64 %0, {%1, %1};" : "=l"(d2) : "f"(pk.z));
        asm("mov.b64 %0, {%1, %1};" : "=l"(d3) : "f"(pk.w));
        asm("fma.rn.f32x2 %0, %1, %2, %0;" : "+l"(acc2[kk][0]) : "l"(u0.x), "l"(d0));
        asm("fma.rn.f32x2 %0, %1, %2, %0;" : "+l"(acc2[kk][1]) : "l"(u0.y), "l"(d0));
        asm("fma.rn.f32x2 %0, %1, %2, %0;" : "+l"(acc2[kk][0]) : "l"(u1.x), "l"(d1));
        asm("fma.rn.f32x2 %0, %1, %2, %0;" : "+l"(acc2[kk][1]) : "l"(u1.y), "l"(d1));
        asm("fma.rn.f32x2 %0, %1, %2, %0;" : "+l"(acc2[kk][0]) : "l"(u2.x), "l"(d2));
        asm("fma.rn.f32x2 %0, %1, %2, %0;" : "+l"(acc2[kk][1]) : "l"(u2.y), "l"(d2));
        asm("fma.rn.f32x2 %0, %1, %2, %0;" : "+l"(acc2[kk][0]) : "l"(u3.x), "l"(d3));
        asm("fma.rn.f32x2 %0, %1, %2, %0;" : "+l"(acc2[kk][1]) : "l"(u3.y), "l"(d3));
    }
}

__global__ void __launch_bounds__(256, 3) match_kernel(
        const float* __restrict__ q, float* __restrict__ out) {
    extern __shared__ __align__(16) char smem_raw[];
    float*              sp  = (float*)smem_raw;              // [K][C] = 64 KB
    unsigned long long* red = (unsigned long long*)smem_raw; // reuse: 16 KB

    const int b     = blockIdx.y;
    const int tid   = threadIdx.x;
    const int slice = tid >> 4;          // 0..15
    const int t     = tid & 15;          // 0..15
    const int kq    = slice & 3;         // protos [kq*4, kq*4+4)
    const int cq    = slice >> 2;        // channels [cq*256, cq*256+256)
    const int p     = blockIdx.x * 64 + t * 4;    // 4 consecutive pixels

    // stage all 16x1024 normalized prototypes
    const float4* pr4 = (const float4*)(g_protoN + (size_t)b * K * C);
    for (int i = tid; i < K * C / 4; i += 256)
        ((float4*)sp)[i] = pr4[i];
    __syncthreads();

    const float* qb  = q + ((size_t)b * C + cq * 256) * HW + p;
    const float* spb = sp + (kq * 4) * C + cq * 256;

    unsigned long long acc2[4][2];   // [kk][pixel-pair]
#pragma unroll
    for (int kk = 0; kk < 4; kk++) { acc2[kk][0] = 0ull; acc2[kk][1] = 0ull; }

    // R11's exact double-buffered pipeline (4-channel batches, A/B rotation)
    float4 a0 = *(const float4*)&qb[(size_t)0 * HW];
    float4 a1 = *(const float4*)&qb[(size_t)1 * HW];
    float4 a2 = *(const float4*)&qb[(size_t)2 * HW];
    float4 a3 = *(const float4*)&qb[(size_t)3 * HW];

#pragma unroll 4
    for (int c = 0; c < 256; c += 8) {
        float4 b0 = *(const float4*)&qb[(size_t)(c + 4) * HW];
        float4 b1 = *(const float4*)&qb[(size_t)(c + 5) * HW];
        float4 b2 = *(const float4*)&qb[(size_t)(c + 6) * HW];
        float4 b3 = *(const float4*)&qb[(size_t)(c + 7) * HW];
        fma_batch(spb, c, a0, a1, a2, a3, acc2);

        if (c + 8 < 256) {
            a0 = *(const float4*)&qb[(size_t)(c +  8) * HW];
            a1 = *(const float4*)&qb[(size_t)(c +  9) * HW];
            a2 = *(const float4*)&qb[(size_t)(c + 10) * HW];
            a3 = *(const float4*)&qb[(size_t)(c + 11) * HW];
        }
        fma_batch(spb, c + 4, b0, b1, b2, b3, acc2);
    }

    // protos dead -> partials in smem, lane-contiguous: red[k][pair][cq][t]
    __syncthreads();
#pragma unroll
    for (int kk = 0; kk < 4; kk++) {
        const int k = kq * 4 + kk;
        red[((k * 2 + 0) * 4 + cq) * 16 + t] = acc2[kk][0];
        red[((k * 2 + 1) * 4 + cq) * 16 + t] = acc2[kk][1];
    }
    __syncthreads();

    // one thread per pixel: sum 4 channel-quarters (packed), pick lane, argmax
    if (tid < 64) {
        const int tt   = tid >> 2;        // source thread
        const int pair = (tid >> 1) & 1;
        const int lohi = tid & 1;
        float best = -3.0e38f;
        int   bi   = 0;
#pragma unroll
        for (int k = 0; k < K; k++) {
            const unsigned long long* r = red + (k * 2 + pair) * 4 * 16 + tt;
            unsigned long long s01, s23, s;
            asm("add.rn.f32x2 %0, %1, %2;" : "=l"(s01) : "l"(r[0]),   "l"(r[16]));
            asm("add.rn.f32x2 %0, %1, %2;" : "=l"(s23) : "l"(r[32]),  "l"(r[48]));
            asm("add.rn.f32x2 %0, %1, %2;" : "=l"(s)   : "l"(s01),    "l"(s23));
            float lo, hi;
            asm("mov.b64 {%0, %1}, %2;" : "=f"(lo), "=f"(hi) : "l"(s));
            const float v = lohi ? hi : lo;
            if (v > best) { best = v; bi = k; }
        }
        out[(size_t)b * HW + blockIdx.x * 64 + tid] = (float)bi;  // f32 output
    }
}

// ---------------------------------------------------------------------------
extern "C" void kernel_launch(void* const* d_in, const int* in_sizes, int n_in,
                              void* d_out, int out_size) {
    // masks is the unique B*HW = 32768-element input; its position fixes the
    // ordering of the two feature tensors.
    int mask_idx = 1;
    for (int i = 0; i < n_in; i++)
        if (in_sizes[i] == B * HW) { mask_idx = i; break; }

    const int*   masks = (const int*)d_in[mask_idx];
    const float* sfeat;
    const float* qfeat;
    if (mask_idx == 1)      { sfeat = (const float*)d_in[0]; qfeat = (const float*)d_in[2]; }
    else if (mask_idx == 2) { qfeat = (const float*)d_in[0]; sfeat = (const float*)d_in[1]; }
    else                    { qfeat = (const float*)d_in[1]; sfeat = (const float*)d_in[2]; }
    float* out = (float*)d_out;
    (void)out_size;

    hist_kernel<<<B, 256>>>(masks);
    proto_sum_kernel<<<dim3(C / 8, B), 256>>>(sfeat, masks);
    finalize_kernel<<<dim3(K, B), 256>>>();

    static int smem_set = 0;
    if (!smem_set) {
        cudaFuncSetAttribute(match_kernel,
                             cudaFuncAttributeMaxDynamicSharedMemorySize,
                             K * C * (int)sizeof(float));
        smem_set = 1;
    }
    match_kernel<<<dim3(HW / 64, B), 256, K * C * sizeof(float)>>>(qfeat, out);
}

// round 17
// speedup vs baseline: 1.3270x; 1.2710x over previous
#include <cuda_runtime.h>

#define B   8
#define C   1024
#define HW  4096
#define K   16

// Scratch (no allocations allowed) — fully rewritten every launch.
__device__ float g_num[B * K * C];      // masked class sums
__device__ float g_protoN[B * K * C];   // prototypes / (count * ||proto||)
__device__ int   g_counts[B * (K + 1)]; // per-class pixel counts (incl. class 0)
__device__ float g_dots[B * K * HW];    // per-(b,k,px) dot values (2 MB)

// ---------------------------------------------------------------------------
// K1: per-batch class histogram of the support mask
// ---------------------------------------------------------------------------
__global__ void __launch_bounds__(256) hist_kernel(const int* __restrict__ masks) {
    __shared__ int h[K + 1];
    const int b   = blockIdx.x;
    const int tid = threadIdx.x;
    if (tid <= K) h[tid] = 0;
    __syncthreads();
    for (int p = tid; p < HW; p += 256) {
        int v = masks[b * HW + p];
        if (v >= 0 && v <= K) atomicAdd(&h[v], 1);   // guarded: never traps
    }
    __syncthreads();
    if (tid <= K) g_counts[b * (K + 1) + tid] = h[tid];
}

// ---------------------------------------------------------------------------
// K2: masked per-class sums.  One warp = one channel; lane-private smem slots
// acc[class][tid] (bank = tid%32 -> conflict-free dynamic indexing).
// 4 float4 loads in flight per lane (2 KB/warp outstanding).
// ---------------------------------------------------------------------------
__global__ void __launch_bounds__(256) proto_sum_kernel(
        const float* __restrict__ feat, const int* __restrict__ masks) {
    __shared__ unsigned char cls[HW];       // 4 KB
    __shared__ float acc[K][256];           // 16 KB

    const int b    = blockIdx.y;
    const int tid  = threadIdx.x;
    const int warp = tid >> 5;
    const int lane = tid & 31;
    const int c    = blockIdx.x * 8 + warp;

#pragma unroll
    for (int k = 0; k < K; k++) acc[k][tid] = 0.0f;
    for (int p = tid; p < HW; p += 256) {
        int v = masks[b * HW + p];
        cls[p] = (unsigned char)((v >= 1 && v <= K) ? v : 0);  // guarded
    }
    __syncthreads();

    const float4* f4 = (const float4*)(feat + ((size_t)b * C + c) * HW);
    const uchar4* c4 = (const uchar4*)cls;

    for (int i = lane; i < HW / 4; i += 128) {
        float4 v0 = f4[i];
        float4 v1 = f4[i + 32];
        float4 v2 = f4[i + 64];
        float4 v3 = f4[i + 96];
        uchar4 m0 = c4[i];
        uchar4 m1 = c4[i + 32];
        uchar4 m2 = c4[i + 64];
        uchar4 m3 = c4[i + 96];
        if (m0.x) acc[m0.x - 1][tid] += v0.x;
        if (m0.y) acc[m0.y - 1][tid] += v0.y;
        if (m0.z) acc[m0.z - 1][tid] += v0.z;
        if (m0.w) acc[m0.w - 1][tid] += v0.w;
        if (m1.x) acc[m1.x - 1][tid] += v1.x;
        if (m1.y) acc[m1.y - 1][tid] += v1.y;
        if (m1.z) acc[m1.z - 1][tid] += v1.z;
        if (m1.w) acc[m1.w - 1][tid] += v1.w;
        if (m2.x) acc[m2.x - 1][tid] += v2.x;
        if (m2.y) acc[m2.y - 1][tid] += v2.y;
        if (m2.z) acc[m2.z - 1][tid] += v2.z;
        if (m2.w) acc[m2.w - 1][tid] += v2.w;
        if (m3.x) acc[m3.x - 1][tid] += v3.x;
        if (m3.y) acc[m3.y - 1][tid] += v3.y;
        if (m3.z) acc[m3.z - 1][tid] += v3.z;
        if (m3.w) acc[m3.w - 1][tid] += v3.w;
    }

#pragma unroll
    for (int k = 0; k < K; k++) {
        float s = acc[k][tid];
#pragma unroll
        for (int off = 16; off; off >>= 1)
            s += __shfl_down_sync(0xffffffffu, s, off);
        if (lane == 0) g_num[((size_t)b * K + k) * C + c] = s;
    }
}

// ---------------------------------------------------------------------------
// K3: g_protoN = (num/count) / ||num/count||.
// argmax_k dot(protoN_k, q) == argmax_k cosine_sim.
// ---------------------------------------------------------------------------
__global__ void __launch_bounds__(256) finalize_kernel() {
    const int b = blockIdx.y, k = blockIdx.x, tid = threadIdx.x;
    const int cnt = g_counts[b * (K + 1) + k + 1];
    const float invCnt = cnt > 0 ? 1.0f / (float)cnt : 0.0f;
    const float* num = g_num    + ((size_t)(b * K + k)) * C;
    float*       out = g_protoN + ((size_t)(b * K + k)) * C;

    float pv[4];
    float ss = 0.0f;
#pragma unroll
    for (int j = 0; j < 4; j++) {
        pv[j] = num[tid + j * 256] * invCnt;
        ss += pv[j] * pv[j];
    }

    __shared__ float red[8];
    __shared__ float s_inv;
#pragma unroll
    for (int off = 16; off; off >>= 1)
        ss += __shfl_down_sync(0xffffffffu, ss, off);
    if ((tid & 31) == 0) red[tid >> 5] = ss;
    __syncthreads();
    if (tid == 0) {
        float s = 0.0f;
#pragma unroll
        for (int w = 0; w < 8; w++) s += red[w];
        s_inv = s > 0.0f ? 1.0f / sqrtf(s) : 0.0f;
    }
    __syncthreads();
    const float inv = s_inv;
#pragma unroll
    for (int j = 0; j < 4; j++) out[tid + j * 256] = pv[j] * inv;
}

// ---------------------------------------------------------------------------
// K4: match, k-half split CTAs.  CTA = 128 threads = 4 cq-slices x 32 t x
// 4 px; blockIdx.y = kh selects which 8 prototypes this CTA owns -> only
// 32 KB smem, so 4 CTAs/SM (128thr x 128regs x 4 = full RF, 4x32KB smem)
// = 16 warps/SM, each running R11's exact 128-reg double-buffered pipeline.
// Per-thread mainloop byte-identical to R11.  Dots written to g_dots; the
// 16-way argmax happens in K5 (identical packed sum order -> same values).
// ---------------------------------------------------------------------------
__device__ __forceinline__ void fma_batch(
        const float* __restrict__ spb, int c,
        const float4& v0, const float4& v1, const float4& v2, const float4& v3,
        unsigned long long (&acc2)[8][2]) {
    const ulonglong2 u0 = *(const ulonglong2*)&v0;   // (p0,p1),(p2,p3)
    const ulonglong2 u1 = *(const ulonglong2*)&v1;
    const ulonglong2 u2 = *(const ulonglong2*)&v2;
    const ulonglong2 u3 = *(const ulonglong2*)&v3;
#pragma unroll
    for (int kk = 0; kk < 8; kk++) {
        const float4 pk = *(const float4*)(spb + kk * C + c);  // LDS.128 bcast
        unsigned long long d0, d1, d2, d3;
        asm("mov.b64 %0, {%1, %1};" : "=l"(d0) : "f"(pk.x));
        asm("mov.b64 %0, {%1, %1};" : "=l"(d1) : "f"(pk.y));
        asm("mov.b64 %0, {%1, %1};" : "=l"(d2) : "f"(pk.z));
        asm("mov.b64 %0, {%1, %1};" : "=l"(d3) : "f"(pk.w));
        asm("fma.rn.f32x2 %0, %1, %2, %0;" : "+l"(acc2[kk][0]) : "l"(u0.x), "l"(d0));
        asm("fma.rn.f32x2 %0, %1, %2, %0;" : "+l"(acc2[kk][1]) : "l"(u0.y), "l"(d0));
        asm("fma.rn.f32x2 %0, %1, %2, %0;" : "+l"(acc2[kk][0]) : "l"(u1.x), "l"(d1));
        asm("fma.rn.f32x2 %0, %1, %2, %0;" : "+l"(acc2[kk][1]) : "l"(u1.y), "l"(d1));
        asm("fma.rn.f32x2 %0, %1, %2, %0;" : "+l"(acc2[kk][0]) : "l"(u2.x), "l"(d2));
        asm("fma.rn.f32x2 %0, %1, %2, %0;" : "+l"(acc2[kk][1]) : "l"(u2.y), "l"(d2));
        asm("fma.rn.f32x2 %0, %1, %2, %0;" : "+l"(acc2[kk][0]) : "l"(u3.x), "l"(d3));
        asm("fma.rn.f32x2 %0, %1, %2, %0;" : "+l"(acc2[kk][1]) : "l"(u3.y), "l"(d3));
    }
}

__global__ void __launch_bounds__(128, 4) match_kernel(const float* __restrict__ q) {
    __shared__ __align__(16) float sp[8 * C];                // 32 KB
    unsigned long long* red = (unsigned long long*)sp;       // reuse: 16 KB

    const int b   = blockIdx.z;
    const int kh  = blockIdx.y;          // k-half: protos [kh*8, kh*8+8)
    const int tid = threadIdx.x;
    const int cq  = tid >> 5;            // 0..3: channels [cq*256, cq*256+256)
    const int t   = tid & 31;            // 0..31
    const int p   = blockIdx.x * 128 + t * 4;   // 4 consecutive pixels

    // stage this CTA's 8 normalized prototypes (8 KB float4s)
    const float4* pr4 = (const float4*)(g_protoN + ((size_t)b * K + kh * 8) * C);
    for (int i = tid; i < 8 * C / 4; i += 128)
        ((float4*)sp)[i] = pr4[i];
    __syncthreads();

    const float* qb  = q + ((size_t)b * C + cq * 256) * HW + p;
    const float* spb = sp + cq * 256;

    unsigned long long acc2[8][2];   // [kk][pixel-pair]
#pragma unroll
    for (int kk = 0; kk < 8; kk++) { acc2[kk][0] = 0ull; acc2[kk][1] = 0ull; }

    // R11's exact double-buffered pipeline (4-channel batches, A/B rotation)
    float4 a0 = *(const float4*)&qb[(size_t)0 * HW];
    float4 a1 = *(const float4*)&qb[(size_t)1 * HW];
    float4 a2 = *(const float4*)&qb[(size_t)2 * HW];
    float4 a3 = *(const float4*)&qb[(size_t)3 * HW];

#pragma unroll 4
    for (int c = 0; c < 256; c += 8) {
        float4 b0 = *(const float4*)&qb[(size_t)(c + 4) * HW];
        float4 b1 = *(const float4*)&qb[(size_t)(c + 5) * HW];
        float4 b2 = *(const float4*)&qb[(size_t)(c + 6) * HW];
        float4 b3 = *(const float4*)&qb[(size_t)(c + 7) * HW];
        fma_batch(spb, c, a0, a1, a2, a3, acc2);

        if (c + 8 < 256) {
            a0 = *(const float4*)&qb[(size_t)(c +  8) * HW];
            a1 = *(const float4*)&qb[(size_t)(c +  9) * HW];
            a2 = *(const float4*)&qb[(size_t)(c + 10) * HW];
            a3 = *(const float4*)&qb[(size_t)(c + 11) * HW];
        }
        fma_batch(spb, c + 4, b0, b1, b2, b3, acc2);
    }

    // protos dead -> partials in smem: red[kk][pair][cq][t]  (16 KB)
    __syncthreads();
#pragma unroll
    for (int kk = 0; kk < 8; kk++) {
        red[((kk * 2 + 0) * 4 + cq) * 32 + t] = acc2[kk][0];
        red[((kk * 2 + 1) * 4 + cq) * 32 + t] = acc2[kk][1];
    }
    __syncthreads();

    // one thread per pixel: packed quarter-sum (q0+q1)+(q2+q3), fold lo+hi
    // last (== R11 order), write dot value per k to g_dots
    {
        const int tt   = tid >> 2;        // source thread
        const int pair = (tid >> 1) & 1;
        const int lohi = tid & 1;
        const int px   = blockIdx.x * 128 + tid;
#pragma unroll
        for (int kk = 0; kk < 8; kk++) {
            const unsigned long long* r = red + (kk * 2 + pair) * 4 * 32 + tt;
            unsigned long long s01, s23, s;
            asm("add.rn.f32x2 %0, %1, %2;" : "=l"(s01) : "l"(r[0]),   "l"(r[32]));
            asm("add.rn.f32x2 %0, %1, %2;" : "=l"(s23) : "l"(r[64]),  "l"(r[96]));
            asm("add.rn.f32x2 %0, %1, %2;" : "=l"(s)   : "l"(s01),    "l"(s23));
            float lo, hi;
            asm("mov.b64 {%0, %1}, %2;" : "=f"(lo), "=f"(hi) : "l"(s));
            g_dots[((size_t)b * K + kh * 8 + kk) * HW + px] = lohi ? hi : lo;
        }
    }
}

// ---------------------------------------------------------------------------
// K5: first-max-wins argmax over 16 dot values per pixel (g_dots is 2 MB,
// L2-resident; reads coalesced along px).  Matches jnp.argmax tie semantics.
// ---------------------------------------------------------------------------
__global__ void __launch_bounds__(256) argmax_kernel(float* __restrict__ out) {
    const int b  = blockIdx.y;
    const int px = blockIdx.x * 256 + threadIdx.x;
    const float* d = g_dots + (size_t)b * K * HW + px;
    float best = -3.0e38f;
    int   bi   = 0;
#pragma unroll
    for (int k = 0; k < K; k++) {
        const float v = d[(size_t)k * HW];
        if (v > best) { best = v; bi = k; }
    }
    out[(size_t)b * HW + px] = (float)bi;   // f32 output
}

// ---------------------------------------------------------------------------
extern "C" void kernel_launch(void* const* d_in, const int* in_sizes, int n_in,
                              void* d_out, int out_size) {
    // masks is the unique B*HW = 32768-element input; its position fixes the
    // ordering of the two feature tensors.
    int mask_idx = 1;
    for (int i = 0; i < n_in; i++)
        if (in_sizes[i] == B * HW) { mask_idx = i; break; }

    const int*   masks = (const int*)d_in[mask_idx];
    const float* sfeat;
    const float* qfeat;
    if (mask_idx == 1)      { sfeat = (const float*)d_in[0]; qfeat = (const float*)d_in[2]; }
    else if (mask_idx == 2) { qfeat = (const float*)d_in[0]; sfeat = (const float*)d_in[1]; }
    else                    { qfeat = (const float*)d_in[1]; sfeat = (const float*)d_in[2]; }
    float* out = (float*)d_out;
    (void)out_size;

    hist_kernel<<<B, 256>>>(masks);
    proto_sum_kernel<<<dim3(C / 8, B), 256>>>(sfeat, masks);
    finalize_kernel<<<dim3(K, B), 256>>>();
    match_kernel<<<dim3(HW / 128, 2, B), 128>>>(qfeat);
    argmax_kernel<<<dim3(HW / 256, B), 256>>>(out);
}